// round 2
// baseline (speedup 1.0000x reference)
#include <cuda_runtime.h>

#define BATCH  8
#define SEQ    1024
#define EMB    768
#define NHEADS 12
#define HDIM   64
#define E3     2304
#define MROWS  8192
#define SCALE  0.125f

// Scratch (no cudaMalloc allowed): QKV buffer 75.5 MB, context 25.2 MB.
__device__ float g_qkv[(size_t)MROWS * E3];
__device__ float g_ctx[(size_t)MROWS * EMB];

// ---------------------------------------------------------------------------
// C[M,N] = A[M,K] @ W[K,N] + bias[N]
// Block tile 64(M) x 128(N), K-tile 16. 256 threads, 4x8 micro-tile/thread.
// As stored transposed [k][m] for conflict-free float4 reads; Bs [k][n].
// M % 64 == 0, N % 128 == 0, K % 16 == 0 hold for all uses here.
// ---------------------------------------------------------------------------
__global__ __launch_bounds__(256) void gemm_bias_kernel(
    const float* __restrict__ A, const float* __restrict__ W,
    const float* __restrict__ bias, float* __restrict__ C,
    int N, int K)
{
    __shared__ float As[16][68];
    __shared__ float Bs[16][132];

    const int tid = threadIdx.x;
    const int tx  = tid & 15;   // 16 col-threads * 8 cols = 128
    const int ty  = tid >> 4;   // 16 row-threads * 4 rows = 64
    const int rowBase = blockIdx.y * 64;
    const int colBase = blockIdx.x * 128;

    // loader mapping
    const int a_m = tid >> 2;          // 0..63
    const int a_k = (tid & 3) << 2;    // 0,4,8,12
    const int b_k = tid >> 5;          // 0..7
    const int b_n = (tid & 31) << 2;   // 0..124

    const float* Aptr = A + (size_t)(rowBase + a_m) * K + a_k;
    const float* Wptr = W + (size_t)b_k * N + colBase + b_n;

    float acc[4][8];
#pragma unroll
    for (int i = 0; i < 4; i++)
#pragma unroll
        for (int j = 0; j < 8; j++) acc[i][j] = 0.f;

    for (int k0 = 0; k0 < K; k0 += 16) {
        float4 av  = *(const float4*)(Aptr + k0);
        float4 bv0 = *(const float4*)(Wptr + (size_t)k0 * N);
        float4 bv1 = *(const float4*)(Wptr + (size_t)(k0 + 8) * N);
        __syncthreads();   // previous tile's compute done before overwrite
        As[a_k + 0][a_m] = av.x;
        As[a_k + 1][a_m] = av.y;
        As[a_k + 2][a_m] = av.z;
        As[a_k + 3][a_m] = av.w;
        *(float4*)&Bs[b_k][b_n]     = bv0;
        *(float4*)&Bs[b_k + 8][b_n] = bv1;
        __syncthreads();

#pragma unroll
        for (int kk = 0; kk < 16; kk++) {
            float4 a  = *(const float4*)&As[kk][ty << 2];
            float4 b0 = *(const float4*)&Bs[kk][tx << 3];
            float4 b1 = *(const float4*)&Bs[kk][(tx << 3) + 4];
            float ar[4] = {a.x, a.y, a.z, a.w};
            float br[8] = {b0.x, b0.y, b0.z, b0.w, b1.x, b1.y, b1.z, b1.w};
#pragma unroll
            for (int i = 0; i < 4; i++)
#pragma unroll
                for (int j = 0; j < 8; j++)
                    acc[i][j] = fmaf(ar[i], br[j], acc[i][j]);
        }
    }

    float bb[8];
    const float* bp = bias + colBase + (tx << 3);
#pragma unroll
    for (int j = 0; j < 8; j++) bb[j] = bp[j];
#pragma unroll
    for (int i = 0; i < 4; i++) {
        float* cp = C + (size_t)(rowBase + (ty << 2) + i) * N + colBase + (tx << 3);
        float4 o0 = make_float4(acc[i][0] + bb[0], acc[i][1] + bb[1],
                                acc[i][2] + bb[2], acc[i][3] + bb[3]);
        float4 o1 = make_float4(acc[i][4] + bb[4], acc[i][5] + bb[5],
                                acc[i][6] + bb[6], acc[i][7] + bb[7]);
        *(float4*)cp       = o0;
        *(float4*)(cp + 4) = o1;
    }
}

// ---------------------------------------------------------------------------
// Flash-attention. Grid (qtile=16, head=12, batch=8), 256 threads (8 warps).
// Each warp owns 8 query rows; each lane owns key/value cols 2*lane, 2*lane+1.
// Q,K transposed in smem ([d][row]) for vectorized broadcast/contiguous reads.
// P tile is warp-private (rows partitioned by warp) -> only __syncwarp needed.
// ---------------------------------------------------------------------------
__global__ __launch_bounds__(256) void attn_kernel(const float* __restrict__ qkv,
                                                   float* __restrict__ ctx)
{
    extern __shared__ float sm[];
    float (*Qts)[68] = (float(*)[68])(sm);                          // [64][68]
    float (*Kts)[66] = (float(*)[66])(sm + 64 * 68);                // [64][66]
    float (*Vs)[66]  = (float(*)[66])(sm + 64 * 68 + 64 * 66);      // [64][66]
    float (*Pts)[66] = (float(*)[66])(sm + 64 * 68 + 2 * 64 * 66);  // [64][66]

    const int tid  = threadIdx.x;
    const int lane = tid & 31;
    const int w    = tid >> 5;
    const int row0 = w << 3;          // 8 query rows per warp
    const int qt = blockIdx.x;
    const int h  = blockIdx.y;
    const int b  = blockIdx.z;

    const int ld_d = tid & 63;        // loader: d index (coalesced 128B/warp)
    const int ld_r = tid >> 6;        // loader: row base (4 rows/pass)

    // ---- load Q tile (transposed) ----
    const float* qbase = qkv + ((size_t)(b * SEQ + qt * 64)) * E3 + h * HDIM;
#pragma unroll
    for (int it = 0; it < 16; it++) {
        int r = ld_r + (it << 2);
        Qts[ld_d][r] = qbase[(size_t)r * E3 + ld_d];
    }

    float m[8], l[8], o0[8], o1[8];
#pragma unroll
    for (int r = 0; r < 8; r++) { m[r] = -1e30f; l[r] = 0.f; o0[r] = 0.f; o1[r] = 0.f; }

    const float* kbase = qkv + (size_t)b * SEQ * E3 + EMB     + h * HDIM;
    const float* vbase = qkv + (size_t)b * SEQ * E3 + 2 * EMB + h * HDIM;

    for (int kt = 0; kt < 16; kt++) {
        __syncthreads();   // previous tile's PV finished
        const float* kb = kbase + (size_t)(kt * 64) * E3;
        const float* vb = vbase + (size_t)(kt * 64) * E3;
#pragma unroll
        for (int it = 0; it < 16; it++) {
            int r = ld_r + (it << 2);
            Kts[ld_d][r] = kb[(size_t)r * E3 + ld_d];
            Vs[r][ld_d]  = vb[(size_t)r * E3 + ld_d];
        }
        __syncthreads();

        // ---- S = Q K^T for this tile ----
        float s0[8], s1[8];
#pragma unroll
        for (int r = 0; r < 8; r++) { s0[r] = 0.f; s1[r] = 0.f; }

#pragma unroll 8
        for (int d = 0; d < 64; d++) {
            float2 kv = *(const float2*)&Kts[d][lane << 1];
            float4 qa = *(const float4*)&Qts[d][row0];
            float4 qb = *(const float4*)&Qts[d][row0 + 4];
            float q[8] = {qa.x, qa.y, qa.z, qa.w, qb.x, qb.y, qb.z, qb.w};
#pragma unroll
            for (int r = 0; r < 8; r++) {
                s0[r] = fmaf(q[r], kv.x, s0[r]);
                s1[r] = fmaf(q[r], kv.y, s1[r]);
            }
        }

        // ---- online softmax update ----
#pragma unroll
        for (int r = 0; r < 8; r++) {
            float sa = s0[r] * SCALE;
            float sb = s1[r] * SCALE;
            float mx = fmaxf(sa, sb);
#pragma unroll
            for (int off = 16; off; off >>= 1)
                mx = fmaxf(mx, __shfl_xor_sync(0xffffffffu, mx, off));
            float mn    = fmaxf(m[r], mx);
            float alpha = __expf(m[r] - mn);
            float p0 = __expf(sa - mn);
            float p1 = __expf(sb - mn);
            float ps = p0 + p1;
#pragma unroll
            for (int off = 16; off; off >>= 1)
                ps += __shfl_xor_sync(0xffffffffu, ps, off);
            l[r] = l[r] * alpha + ps;
            m[r] = mn;
            o0[r] *= alpha;
            o1[r] *= alpha;
            Pts[(lane << 1)][row0 + r]     = p0;   // P stored transposed [kcol][qrow]
            Pts[(lane << 1) + 1][row0 + r] = p1;
        }
        __syncwarp();   // P rows are warp-private; warp-level visibility suffices

        // ---- O += P V ----
#pragma unroll 8
        for (int j = 0; j < 64; j++) {
            float2 v  = *(const float2*)&Vs[j][lane << 1];
            float2 pa = *(const float2*)&Pts[j][row0];
            float2 pb = *(const float2*)&Pts[j][row0 + 2];
            float2 pc = *(const float2*)&Pts[j][row0 + 4];
            float2 pd = *(const float2*)&Pts[j][row0 + 6];
            float p[8] = {pa.x, pa.y, pb.x, pb.y, pc.x, pc.y, pd.x, pd.y};
#pragma unroll
            for (int r = 0; r < 8; r++) {
                o0[r] = fmaf(p[r], v.x, o0[r]);
                o1[r] = fmaf(p[r], v.y, o1[r]);
            }
        }
    }

    // ---- normalize and write ctx[b, t, h*64 + d] ----
    float* obase = ctx + ((size_t)(b * SEQ + qt * 64)) * EMB + h * HDIM + (lane << 1);
#pragma unroll
    for (int r = 0; r < 8; r++) {
        float inv = 1.f / l[r];
        float2 ov = make_float2(o0[r] * inv, o1[r] * inv);
        *(float2*)(obase + (size_t)(row0 + r) * EMB) = ov;
    }
}

// ---------------------------------------------------------------------------
extern "C" void kernel_launch(void* const* d_in, const int* in_sizes, int n_in,
                              void* d_out, int out_size)
{
    const float* hs     = (const float*)d_in[0];
    const float* qkv_w  = (const float*)d_in[1];
    const float* qkv_b  = (const float*)d_in[2];
    const float* proj_w = (const float*)d_in[3];
    const float* proj_b = (const float*)d_in[4];
    float* out = (float*)d_out;

    float *qkvbuf, *ctxbuf;
    cudaGetSymbolAddress((void**)&qkvbuf, g_qkv);
    cudaGetSymbolAddress((void**)&ctxbuf, g_ctx);

    // 1) QKV projection: [8192,768] @ [768,2304]
    gemm_bias_kernel<<<dim3(E3 / 128, MROWS / 64), 256>>>(hs, qkv_w, qkv_b, qkvbuf, E3, EMB);

    // 2) fused attention
    const int attn_smem = (64 * 68 + 3 * 64 * 66) * (int)sizeof(float);  // 68096 B
    cudaFuncSetAttribute(attn_kernel, cudaFuncAttributeMaxDynamicSharedMemorySize, attn_smem);
    attn_kernel<<<dim3(SEQ / 64, NHEADS, BATCH), 256, attn_smem>>>(qkvbuf, ctxbuf);

    // 3) output projection: [8192,768] @ [768,768]
    gemm_bias_kernel<<<dim3(EMB / 128, MROWS / 64), 256>>>(ctxbuf, proj_w, proj_b, out, EMB, EMB);
}

// round 3
// speedup vs baseline: 1.9352x; 1.9352x over previous
#include <cuda_runtime.h>

#define BATCH  8
#define SEQ    1024
#define EMB    768
#define NHEADS 12
#define HDIM   64
#define E3     2304
#define MROWS  8192
#define SCALE  0.125f

// Scratch (no cudaMalloc allowed): QKV buffer 75.5 MB, context 25.2 MB.
__device__ float g_qkv[(size_t)MROWS * E3];
__device__ float g_ctx[(size_t)MROWS * EMB];

// ---------------------------------------------------------------------------
// tf32 helpers
// ---------------------------------------------------------------------------
__device__ __forceinline__ unsigned f2tf32(float x) {
    unsigned r;
    asm("cvt.rna.tf32.f32 %0, %1;" : "=r"(r) : "f"(x));
    return r;
}

__device__ __forceinline__ void mma_tf32(float* d, const unsigned* a, const unsigned* b) {
    asm volatile(
        "mma.sync.aligned.m16n8k8.row.col.f32.tf32.tf32.f32 "
        "{%0,%1,%2,%3}, {%4,%5,%6,%7}, {%8,%9}, {%0,%1,%2,%3};\n"
        : "+f"(d[0]), "+f"(d[1]), "+f"(d[2]), "+f"(d[3])
        : "r"(a[0]), "r"(a[1]), "r"(a[2]), "r"(a[3]), "r"(b[0]), "r"(b[1]));
}

// ---------------------------------------------------------------------------
// C[M,N] = A[M,K] @ W[K,N] + bias[N], tf32 tensor cores.
// CTA tile 128x128, BK=16. 256 threads = 8 warps in 2(m) x 4(n);
// warp tile 64x32 = 4x4 m16n8k8 tiles.
// As[m][k] stride 20 and Bs[k][n] stride 136 give conflict-free frag LDS.
// Requires M%128==0, N%128==0, K%16==0 (true for all 3 uses).
// ---------------------------------------------------------------------------
__global__ __launch_bounds__(256) void gemm_tf32_kernel(
    const float* __restrict__ A, const float* __restrict__ W,
    const float* __restrict__ bias, float* __restrict__ C,
    int N, int K)
{
    __shared__ unsigned As[128 * 20];   // [m][k], stride 20
    __shared__ unsigned Bs[16 * 136];   // [k][n], stride 136

    const int tid  = threadIdx.x;
    const int lane = tid & 31;
    const int wid  = tid >> 5;
    const int wm   = wid >> 2;          // 0..1
    const int wn   = wid & 3;           // 0..3
    const int r0   = lane >> 2;         // 0..7
    const int c0   = lane & 3;          // 0..3
    const int rowBase = blockIdx.y * 128;
    const int colBase = blockIdx.x * 128;

    // loader mappings (2 float4 per thread per tile for each of A and B)
    const int a_row = tid >> 2;               // 0..63 (+64 second pass)
    const int a_kf  = (tid & 3) << 2;         // 0,4,8,12
    const int b_k   = tid >> 5;               // 0..7 (+8 second pass)
    const int b_n   = (lane) << 2;            // 0..124

    const float* Ap = A + (size_t)(rowBase + a_row) * K + a_kf;
    const float* Wp = W + (size_t)b_k * N + colBase + b_n;

    float acc[4][4][4];
#pragma unroll
    for (int i = 0; i < 4; i++)
#pragma unroll
        for (int j = 0; j < 4; j++)
#pragma unroll
            for (int e = 0; e < 4; e++) acc[i][j][e] = 0.f;

    const int nkt = K / 16;
    float4 aIn[2], bIn[2];

    // preload tile 0
    aIn[0] = *(const float4*)(Ap);
    aIn[1] = *(const float4*)(Ap + (size_t)64 * K);
    bIn[0] = *(const float4*)(Wp);
    bIn[1] = *(const float4*)(Wp + (size_t)8 * N);

    for (int kt = 0; kt < nkt; kt++) {
        // store staged tile to smem (tf32-converted, RNA)
#pragma unroll
        for (int p = 0; p < 2; p++) {
            unsigned* as = &As[(a_row + p * 64) * 20 + a_kf];
            as[0] = f2tf32(aIn[p].x); as[1] = f2tf32(aIn[p].y);
            as[2] = f2tf32(aIn[p].z); as[3] = f2tf32(aIn[p].w);
            unsigned* bs = &Bs[(b_k + p * 8) * 136 + b_n];
            bs[0] = f2tf32(bIn[p].x); bs[1] = f2tf32(bIn[p].y);
            bs[2] = f2tf32(bIn[p].z); bs[3] = f2tf32(bIn[p].w);
        }
        __syncthreads();

        // prefetch next tile
        if (kt + 1 < nkt) {
            const float* Apn = Ap + (kt + 1) * 16;
            const float* Wpn = Wp + (size_t)(kt + 1) * 16 * N;
            aIn[0] = *(const float4*)(Apn);
            aIn[1] = *(const float4*)(Apn + (size_t)64 * K);
            bIn[0] = *(const float4*)(Wpn);
            bIn[1] = *(const float4*)(Wpn + (size_t)8 * N);
        }

        // compute 2 k8 sub-steps
#pragma unroll
        for (int k8 = 0; k8 < 16; k8 += 8) {
            unsigned af[4][4], bf[4][2];
#pragma unroll
            for (int mt = 0; mt < 4; mt++) {
                int row = wm * 64 + mt * 16 + r0;
                af[mt][0] = As[row * 20 + k8 + c0];
                af[mt][1] = As[(row + 8) * 20 + k8 + c0];
                af[mt][2] = As[row * 20 + k8 + 4 + c0];
                af[mt][3] = As[(row + 8) * 20 + k8 + 4 + c0];
            }
#pragma unroll
            for (int nt = 0; nt < 4; nt++) {
                int col = wn * 32 + nt * 8 + r0;
                bf[nt][0] = Bs[(k8 + c0) * 136 + col];
                bf[nt][1] = Bs[(k8 + 4 + c0) * 136 + col];
            }
#pragma unroll
            for (int mt = 0; mt < 4; mt++)
#pragma unroll
                for (int nt = 0; nt < 4; nt++)
                    mma_tf32(acc[mt][nt], af[mt], bf[nt]);
        }
        __syncthreads();
    }

    // epilogue: bias + store (float2 per half-tile row)
#pragma unroll
    for (int nt = 0; nt < 4; nt++) {
        int col = colBase + wn * 32 + nt * 8 + (c0 << 1);
        float2 bv = *(const float2*)(bias + col);
#pragma unroll
        for (int mt = 0; mt < 4; mt++) {
            int row = rowBase + wm * 64 + mt * 16 + r0;
            float2 o0 = make_float2(acc[mt][nt][0] + bv.x, acc[mt][nt][1] + bv.y);
            float2 o1 = make_float2(acc[mt][nt][2] + bv.x, acc[mt][nt][3] + bv.y);
            *(float2*)(C + (size_t)row * N + col)       = o0;
            *(float2*)(C + (size_t)(row + 8) * N + col) = o1;
        }
    }
}

// ---------------------------------------------------------------------------
// Flash-attention (unchanged from R2). Grid (16, 12, 8), 256 threads.
// ---------------------------------------------------------------------------
__global__ __launch_bounds__(256) void attn_kernel(const float* __restrict__ qkv,
                                                   float* __restrict__ ctx)
{
    extern __shared__ float sm[];
    float (*Qts)[68] = (float(*)[68])(sm);                          // [64][68]
    float (*Kts)[66] = (float(*)[66])(sm + 64 * 68);                // [64][66]
    float (*Vs)[66]  = (float(*)[66])(sm + 64 * 68 + 64 * 66);      // [64][66]
    float (*Pts)[66] = (float(*)[66])(sm + 64 * 68 + 2 * 64 * 66);  // [64][66]

    const int tid  = threadIdx.x;
    const int lane = tid & 31;
    const int w    = tid >> 5;
    const int row0 = w << 3;
    const int qt = blockIdx.x;
    const int h  = blockIdx.y;
    const int b  = blockIdx.z;

    const int ld_d = tid & 63;
    const int ld_r = tid >> 6;

    const float* qbase = qkv + ((size_t)(b * SEQ + qt * 64)) * E3 + h * HDIM;
#pragma unroll
    for (int it = 0; it < 16; it++) {
        int r = ld_r + (it << 2);
        Qts[ld_d][r] = qbase[(size_t)r * E3 + ld_d];
    }

    float m[8], l[8], o0[8], o1[8];
#pragma unroll
    for (int r = 0; r < 8; r++) { m[r] = -1e30f; l[r] = 0.f; o0[r] = 0.f; o1[r] = 0.f; }

    const float* kbase = qkv + (size_t)b * SEQ * E3 + EMB     + h * HDIM;
    const float* vbase = qkv + (size_t)b * SEQ * E3 + 2 * EMB + h * HDIM;

    for (int kt = 0; kt < 16; kt++) {
        __syncthreads();
        const float* kb = kbase + (size_t)(kt * 64) * E3;
        const float* vb = vbase + (size_t)(kt * 64) * E3;
#pragma unroll
        for (int it = 0; it < 16; it++) {
            int r = ld_r + (it << 2);
            Kts[ld_d][r] = kb[(size_t)r * E3 + ld_d];
            Vs[r][ld_d]  = vb[(size_t)r * E3 + ld_d];
        }
        __syncthreads();

        float s0[8], s1[8];
#pragma unroll
        for (int r = 0; r < 8; r++) { s0[r] = 0.f; s1[r] = 0.f; }

#pragma unroll 8
        for (int d = 0; d < 64; d++) {
            float2 kv = *(const float2*)&Kts[d][lane << 1];
            float4 qa = *(const float4*)&Qts[d][row0];
            float4 qb = *(const float4*)&Qts[d][row0 + 4];
            float q[8] = {qa.x, qa.y, qa.z, qa.w, qb.x, qb.y, qb.z, qb.w};
#pragma unroll
            for (int r = 0; r < 8; r++) {
                s0[r] = fmaf(q[r], kv.x, s0[r]);
                s1[r] = fmaf(q[r], kv.y, s1[r]);
            }
        }

#pragma unroll
        for (int r = 0; r < 8; r++) {
            float sa = s0[r] * SCALE;
            float sb = s1[r] * SCALE;
            float mx = fmaxf(sa, sb);
#pragma unroll
            for (int off = 16; off; off >>= 1)
                mx = fmaxf(mx, __shfl_xor_sync(0xffffffffu, mx, off));
            float mn    = fmaxf(m[r], mx);
            float alpha = __expf(m[r] - mn);
            float p0 = __expf(sa - mn);
            float p1 = __expf(sb - mn);
            float ps = p0 + p1;
#pragma unroll
            for (int off = 16; off; off >>= 1)
                ps += __shfl_xor_sync(0xffffffffu, ps, off);
            l[r] = l[r] * alpha + ps;
            m[r] = mn;
            o0[r] *= alpha;
            o1[r] *= alpha;
            Pts[(lane << 1)][row0 + r]     = p0;
            Pts[(lane << 1) + 1][row0 + r] = p1;
        }
        __syncwarp();

#pragma unroll 8
        for (int j = 0; j < 64; j++) {
            float2 v  = *(const float2*)&Vs[j][lane << 1];
            float2 pa = *(const float2*)&Pts[j][row0];
            float2 pb = *(const float2*)&Pts[j][row0 + 2];
            float2 pc = *(const float2*)&Pts[j][row0 + 4];
            float2 pd = *(const float2*)&Pts[j][row0 + 6];
            float p[8] = {pa.x, pa.y, pb.x, pb.y, pc.x, pc.y, pd.x, pd.y};
#pragma unroll
            for (int r = 0; r < 8; r++) {
                o0[r] = fmaf(p[r], v.x, o0[r]);
                o1[r] = fmaf(p[r], v.y, o1[r]);
            }
        }
    }

    float* obase = ctx + ((size_t)(b * SEQ + qt * 64)) * EMB + h * HDIM + (lane << 1);
#pragma unroll
    for (int r = 0; r < 8; r++) {
        float inv = 1.f / l[r];
        float2 ov = make_float2(o0[r] * inv, o1[r] * inv);
        *(float2*)(obase + (size_t)(row0 + r) * EMB) = ov;
    }
}

// ---------------------------------------------------------------------------
extern "C" void kernel_launch(void* const* d_in, const int* in_sizes, int n_in,
                              void* d_out, int out_size)
{
    const float* hs     = (const float*)d_in[0];
    const float* qkv_w  = (const float*)d_in[1];
    const float* qkv_b  = (const float*)d_in[2];
    const float* proj_w = (const float*)d_in[3];
    const float* proj_b = (const float*)d_in[4];
    float* out = (float*)d_out;

    float *qkvbuf, *ctxbuf;
    cudaGetSymbolAddress((void**)&qkvbuf, g_qkv);
    cudaGetSymbolAddress((void**)&ctxbuf, g_ctx);

    // 1) QKV projection: [8192,768] @ [768,2304]
    gemm_tf32_kernel<<<dim3(E3 / 128, MROWS / 128), 256>>>(hs, qkv_w, qkv_b, qkvbuf, E3, EMB);

    // 2) fused attention
    const int attn_smem = (64 * 68 + 3 * 64 * 66) * (int)sizeof(float);  // 68096 B
    cudaFuncSetAttribute(attn_kernel, cudaFuncAttributeMaxDynamicSharedMemorySize, attn_smem);
    attn_kernel<<<dim3(SEQ / 64, NHEADS, BATCH), 256, attn_smem>>>(qkvbuf, ctxbuf);

    // 3) output projection: [8192,768] @ [768,768]
    gemm_tf32_kernel<<<dim3(EMB / 128, MROWS / 128), 256>>>(ctxbuf, proj_w, proj_b, out, EMB, EMB);
}

// round 5
// speedup vs baseline: 3.3274x; 1.7194x over previous
#include <cuda_runtime.h>

#define BATCH  8
#define SEQ    1024
#define EMB    768
#define NHEADS 12
#define HDIM   64
#define E3     2304
#define MROWS  8192
#define SCALE  0.125f

// Scratch (no cudaMalloc allowed): QKV buffer 75.5 MB, context 25.2 MB.
__device__ float g_qkv[(size_t)MROWS * E3];
__device__ float g_ctx[(size_t)MROWS * EMB];

// ---------------------------------------------------------------------------
// tf32 helpers
// ---------------------------------------------------------------------------
__device__ __forceinline__ unsigned f2tf32(float x) {
    unsigned r;
    asm("cvt.rna.tf32.f32 %0, %1;" : "=r"(r) : "f"(x));
    return r;
}

__device__ __forceinline__ void mma_tf32(float* d, const unsigned* a, const unsigned* b) {
    asm volatile(
        "mma.sync.aligned.m16n8k8.row.col.f32.tf32.tf32.f32 "
        "{%0,%1,%2,%3}, {%4,%5,%6,%7}, {%8,%9}, {%0,%1,%2,%3};\n"
        : "+f"(d[0]), "+f"(d[1]), "+f"(d[2]), "+f"(d[3])
        : "r"(a[0]), "r"(a[1]), "r"(a[2]), "r"(a[3]), "r"(b[0]), "r"(b[1]));
}

// ---------------------------------------------------------------------------
// C[M,N] = A[M,K] @ W[K,N] + bias[N], tf32 tensor cores. (unchanged from R3)
// ---------------------------------------------------------------------------
__global__ __launch_bounds__(256) void gemm_tf32_kernel(
    const float* __restrict__ A, const float* __restrict__ W,
    const float* __restrict__ bias, float* __restrict__ C,
    int N, int K)
{
    __shared__ unsigned As[128 * 20];   // [m][k], stride 20
    __shared__ unsigned Bs[16 * 136];   // [k][n], stride 136

    const int tid  = threadIdx.x;
    const int lane = tid & 31;
    const int wid  = tid >> 5;
    const int wm   = wid >> 2;
    const int wn   = wid & 3;
    const int r0   = lane >> 2;
    const int c0   = lane & 3;
    const int rowBase = blockIdx.y * 128;
    const int colBase = blockIdx.x * 128;

    const int a_row = tid >> 2;
    const int a_kf  = (tid & 3) << 2;
    const int b_k   = tid >> 5;
    const int b_n   = (lane) << 2;

    const float* Ap = A + (size_t)(rowBase + a_row) * K + a_kf;
    const float* Wp = W + (size_t)b_k * N + colBase + b_n;

    float acc[4][4][4];
#pragma unroll
    for (int i = 0; i < 4; i++)
#pragma unroll
        for (int j = 0; j < 4; j++)
#pragma unroll
            for (int e = 0; e < 4; e++) acc[i][j][e] = 0.f;

    const int nkt = K / 16;
    float4 aIn[2], bIn[2];

    aIn[0] = *(const float4*)(Ap);
    aIn[1] = *(const float4*)(Ap + (size_t)64 * K);
    bIn[0] = *(const float4*)(Wp);
    bIn[1] = *(const float4*)(Wp + (size_t)8 * N);

    for (int kt = 0; kt < nkt; kt++) {
#pragma unroll
        for (int p = 0; p < 2; p++) {
            unsigned* as = &As[(a_row + p * 64) * 20 + a_kf];
            as[0] = f2tf32(aIn[p].x); as[1] = f2tf32(aIn[p].y);
            as[2] = f2tf32(aIn[p].z); as[3] = f2tf32(aIn[p].w);
            unsigned* bs = &Bs[(b_k + p * 8) * 136 + b_n];
            bs[0] = f2tf32(bIn[p].x); bs[1] = f2tf32(bIn[p].y);
            bs[2] = f2tf32(bIn[p].z); bs[3] = f2tf32(bIn[p].w);
        }
        __syncthreads();

        if (kt + 1 < nkt) {
            const float* Apn = Ap + (kt + 1) * 16;
            const float* Wpn = Wp + (size_t)(kt + 1) * 16 * N;
            aIn[0] = *(const float4*)(Apn);
            aIn[1] = *(const float4*)(Apn + (size_t)64 * K);
            bIn[0] = *(const float4*)(Wpn);
            bIn[1] = *(const float4*)(Wpn + (size_t)8 * N);
        }

#pragma unroll
        for (int k8 = 0; k8 < 16; k8 += 8) {
            unsigned af[4][4], bf[4][2];
#pragma unroll
            for (int mt = 0; mt < 4; mt++) {
                int row = wm * 64 + mt * 16 + r0;
                af[mt][0] = As[row * 20 + k8 + c0];
                af[mt][1] = As[(row + 8) * 20 + k8 + c0];
                af[mt][2] = As[row * 20 + k8 + 4 + c0];
                af[mt][3] = As[(row + 8) * 20 + k8 + 4 + c0];
            }
#pragma unroll
            for (int nt = 0; nt < 4; nt++) {
                int col = wn * 32 + nt * 8 + r0;
                bf[nt][0] = Bs[(k8 + c0) * 136 + col];
                bf[nt][1] = Bs[(k8 + 4 + c0) * 136 + col];
            }
#pragma unroll
            for (int mt = 0; mt < 4; mt++)
#pragma unroll
                for (int nt = 0; nt < 4; nt++)
                    mma_tf32(acc[mt][nt], af[mt], bf[nt]);
        }
        __syncthreads();
    }

#pragma unroll
    for (int nt = 0; nt < 4; nt++) {
        int col = colBase + wn * 32 + nt * 8 + (c0 << 1);
        float2 bv = *(const float2*)(bias + col);
#pragma unroll
        for (int mt = 0; mt < 4; mt++) {
            int row = rowBase + wm * 64 + mt * 16 + r0;
            float2 o0 = make_float2(acc[mt][nt][0] + bv.x, acc[mt][nt][1] + bv.y);
            float2 o1 = make_float2(acc[mt][nt][2] + bv.x, acc[mt][nt][3] + bv.y);
            *(float2*)(C + (size_t)row * N + col)       = o0;
            *(float2*)(C + (size_t)(row + 8) * N + col) = o1;
        }
    }
}

// ---------------------------------------------------------------------------
// Tensor-core flash attention.
// Grid (8 qtiles, 12 heads, 8 batch), 256 threads = 8 warps.
// CTA tile: 128 q-rows. Key loop: 16 tiles of 64 keys.
// Warp w owns q-rows [16w, 16w+16): softmax = quad shfl; P is warp-private.
// Q fragments hoisted to registers; Q smem region reused as P buffer.
// Smem strides: Qs/Ks/Ps 68 (4*r0+c0 -> 32 banks), Vs 72 (8*c0+r0 -> 32 banks).
// ---------------------------------------------------------------------------
__global__ __launch_bounds__(256) void attn_tc_kernel(const float* __restrict__ qkv,
                                                      float* __restrict__ ctx)
{
    extern __shared__ unsigned smu[];
    unsigned* Qs = smu;                     // [128][68]  (reused as Ps)
    unsigned* Ks = smu + 128 * 68;          // [64][68]
    unsigned* Vs = Ks + 64 * 68;            // [64][72]
    unsigned* Ps = Qs;

    const int tid  = threadIdx.x;
    const int lane = tid & 31;
    const int w    = tid >> 5;
    const int r0   = lane >> 2;
    const int c0   = lane & 3;
    const int qrow = w * 16 + r0;           // this thread's base q-row

    const int qt = blockIdx.x;
    const int h  = blockIdx.y;
    const int b  = blockIdx.z;

    // loader mapping: row = (tid>>4) + 16*it, 4 cols from 4*(tid&15)
    const int lrow = tid >> 4;
    const int lcol = (tid & 15) << 2;

    // ---- load Q tile (prescaled by SCALE, tf32) ----
    const float* qbase = qkv + (size_t)(b * SEQ + qt * 128) * E3 + h * HDIM;
#pragma unroll
    for (int it = 0; it < 8; it++) {
        int row = lrow + it * 16;
        float4 v = *(const float4*)(qbase + (size_t)row * E3 + lcol);
        uint4 u = make_uint4(f2tf32(v.x * SCALE), f2tf32(v.y * SCALE),
                             f2tf32(v.z * SCALE), f2tf32(v.w * SCALE));
        *(uint4*)&Qs[row * 68 + lcol] = u;
    }
    __syncthreads();

    // ---- hoist Q fragments (16 rows x 64 d = 8 k-steps) ----
    unsigned qf[8][4];
#pragma unroll
    for (int kk = 0; kk < 8; kk++) {
        qf[kk][0] = Qs[qrow * 68 + kk * 8 + c0];
        qf[kk][1] = Qs[(qrow + 8) * 68 + kk * 8 + c0];
        qf[kk][2] = Qs[qrow * 68 + kk * 8 + c0 + 4];
        qf[kk][3] = Qs[(qrow + 8) * 68 + kk * 8 + c0 + 4];
    }

    float accO[8][4];
#pragma unroll
    for (int nt = 0; nt < 8; nt++)
#pragma unroll
        for (int e = 0; e < 4; e++) accO[nt][e] = 0.f;
    float m0 = -1e30f, m1 = -1e30f, l0 = 0.f, l1 = 0.f;

    const float* kbase = qkv + (size_t)b * SEQ * E3 + EMB     + h * HDIM;
    const float* vbase = qkv + (size_t)b * SEQ * E3 + 2 * EMB + h * HDIM;

    for (int kt = 0; kt < 16; kt++) {
        __syncthreads();   // Vs/Qs-frag consumers done before overwrite
        const float* kb = kbase + (size_t)(kt * 64) * E3;
        const float* vb = vbase + (size_t)(kt * 64) * E3;
#pragma unroll
        for (int it = 0; it < 4; it++) {
            int row = lrow + it * 16;
            float4 kv = *(const float4*)(kb + (size_t)row * E3 + lcol);
            float4 vv = *(const float4*)(vb + (size_t)row * E3 + lcol);
            *(uint4*)&Ks[row * 68 + lcol] =
                make_uint4(f2tf32(kv.x), f2tf32(kv.y), f2tf32(kv.z), f2tf32(kv.w));
            *(uint4*)&Vs[row * 72 + lcol] =
                make_uint4(f2tf32(vv.x), f2tf32(vv.y), f2tf32(vv.z), f2tf32(vv.w));
        }
        __syncthreads();

        // ---- S = Q K^T : 16 rows x 64 keys per warp ----
        float accS[8][4];
#pragma unroll
        for (int nt = 0; nt < 8; nt++)
#pragma unroll
            for (int e = 0; e < 4; e++) accS[nt][e] = 0.f;

#pragma unroll
        for (int kk = 0; kk < 8; kk++) {
#pragma unroll
            for (int nt = 0; nt < 8; nt++) {
                unsigned bf[2];
                bf[0] = Ks[(nt * 8 + r0) * 68 + kk * 8 + c0];
                bf[1] = Ks[(nt * 8 + r0) * 68 + kk * 8 + c0 + 4];
                mma_tf32(accS[nt], qf[kk], bf);
            }
        }

        // ---- online softmax (rows qrow, qrow+8) ----
        float mx0 = -1e30f, mx1 = -1e30f;
#pragma unroll
        for (int nt = 0; nt < 8; nt++) {
            mx0 = fmaxf(mx0, fmaxf(accS[nt][0], accS[nt][1]));
            mx1 = fmaxf(mx1, fmaxf(accS[nt][2], accS[nt][3]));
        }
#pragma unroll
        for (int off = 1; off < 4; off <<= 1) {
            mx0 = fmaxf(mx0, __shfl_xor_sync(0xffffffffu, mx0, off));
            mx1 = fmaxf(mx1, __shfl_xor_sync(0xffffffffu, mx1, off));
        }
        float mn0 = fmaxf(m0, mx0), mn1 = fmaxf(m1, mx1);
        float alpha0 = __expf(m0 - mn0), alpha1 = __expf(m1 - mn1);
        m0 = mn0; m1 = mn1;

        __syncwarp();   // lagging lanes must finish prior PV reads of Ps

        float s0 = 0.f, s1 = 0.f;
#pragma unroll
        for (int nt = 0; nt < 8; nt++) {
            float p0 = __expf(accS[nt][0] - mn0);
            float p1 = __expf(accS[nt][1] - mn0);
            float p2 = __expf(accS[nt][2] - mn1);
            float p3 = __expf(accS[nt][3] - mn1);
            s0 += p0 + p1;
            s1 += p2 + p3;
            int cl = nt * 8 + (c0 << 1);
            Ps[qrow * 68 + cl]           = f2tf32(p0);
            Ps[qrow * 68 + cl + 1]       = f2tf32(p1);
            Ps[(qrow + 8) * 68 + cl]     = f2tf32(p2);
            Ps[(qrow + 8) * 68 + cl + 1] = f2tf32(p3);
        }
#pragma unroll
        for (int off = 1; off < 4; off <<= 1) {
            s0 += __shfl_xor_sync(0xffffffffu, s0, off);
            s1 += __shfl_xor_sync(0xffffffffu, s1, off);
        }
        l0 = l0 * alpha0 + s0;
        l1 = l1 * alpha1 + s1;
#pragma unroll
        for (int nt = 0; nt < 8; nt++) {
            accO[nt][0] *= alpha0; accO[nt][1] *= alpha0;
            accO[nt][2] *= alpha1; accO[nt][3] *= alpha1;
        }
        __syncwarp();   // P rows are warp-private: warp visibility suffices

        // ---- O += P V : A = P[16x64], B = V[64keys x 64d] ----
#pragma unroll
        for (int kk = 0; kk < 8; kk++) {
            unsigned af[4];
            af[0] = Ps[qrow * 68 + kk * 8 + c0];
            af[1] = Ps[(qrow + 8) * 68 + kk * 8 + c0];
            af[2] = Ps[qrow * 68 + kk * 8 + c0 + 4];
            af[3] = Ps[(qrow + 8) * 68 + kk * 8 + c0 + 4];
#pragma unroll
            for (int nt = 0; nt < 8; nt++) {
                unsigned bf[2];
                bf[0] = Vs[(kk * 8 + c0) * 72 + nt * 8 + r0];
                bf[1] = Vs[(kk * 8 + c0 + 4) * 72 + nt * 8 + r0];
                mma_tf32(accO[nt], af, bf);
            }
        }
    }

    // ---- normalize + write ctx[b, t, h*64 + d] ----
    float inv0 = 1.f / l0, inv1 = 1.f / l1;
    float* obase = ctx + (size_t)(b * SEQ + qt * 128) * EMB + h * HDIM;
#pragma unroll
    for (int nt = 0; nt < 8; nt++) {
        int col = nt * 8 + (c0 << 1);
        *(float2*)(obase + (size_t)qrow * EMB + col) =
            make_float2(accO[nt][0] * inv0, accO[nt][1] * inv0);
        *(float2*)(obase + (size_t)(qrow + 8) * EMB + col) =
            make_float2(accO[nt][2] * inv1, accO[nt][3] * inv1);
    }
}

// ---------------------------------------------------------------------------
extern "C" void kernel_launch(void* const* d_in, const int* in_sizes, int n_in,
                              void* d_out, int out_size)
{
    const float* hs     = (const float*)d_in[0];
    const float* qkv_w  = (const float*)d_in[1];
    const float* qkv_b  = (const float*)d_in[2];
    const float* proj_w = (const float*)d_in[3];
    const float* proj_b = (const float*)d_in[4];
    float* out = (float*)d_out;

    float *qkvbuf, *ctxbuf;
    cudaGetSymbolAddress((void**)&qkvbuf, g_qkv);
    cudaGetSymbolAddress((void**)&ctxbuf, g_ctx);

    // 1) QKV projection: [8192,768] @ [768,2304]
    gemm_tf32_kernel<<<dim3(E3 / 128, MROWS / 128), 256>>>(hs, qkv_w, qkv_b, qkvbuf, E3, EMB);

    // 2) tensor-core flash attention
    const int attn_smem = (128 * 68 + 64 * 68 + 64 * 72) * (int)sizeof(unsigned);  // 70656 B
    cudaFuncSetAttribute(attn_tc_kernel, cudaFuncAttributeMaxDynamicSharedMemorySize, attn_smem);
    attn_tc_kernel<<<dim3(SEQ / 128, NHEADS, BATCH), 256, attn_smem>>>(qkvbuf, ctxbuf);

    // 3) output projection: [8192,768] @ [768,768]
    gemm_tf32_kernel<<<dim3(EMB / 128, MROWS / 128), 256>>>(ctxbuf, proj_w, proj_b, out, EMB, EMB);
}

// round 6
// speedup vs baseline: 6.1285x; 1.8418x over previous
#include <cuda_runtime.h>
#include <cuda_fp16.h>

#define BATCH  8
#define SEQ    1024
#define EMB    768
#define NHEADS 12
#define HDIM   64
#define E3     2304
#define MROWS  8192
#define SCALE  0.125f

// Scratch (no cudaMalloc allowed)
__device__ __half g_hs16[(size_t)MROWS * EMB];     // hidden fp16
__device__ __half g_qkvwt[(size_t)E3 * EMB];       // qkv_w^T  [n][k] fp16
__device__ __half g_projwt[(size_t)EMB * EMB];     // proj_w^T [n][k] fp16
__device__ __half g_qkv16[(size_t)MROWS * E3];     // QKV output fp16 (Q pre-scaled)
__device__ __half g_ctx16[(size_t)MROWS * EMB];    // attention output fp16

// ---------------------------------------------------------------------------
// helpers
// ---------------------------------------------------------------------------
__device__ __forceinline__ void mma_f16(float* d, const unsigned* a, const unsigned* b) {
    asm volatile(
        "mma.sync.aligned.m16n8k16.row.col.f32.f16.f16.f32 "
        "{%0,%1,%2,%3}, {%4,%5,%6,%7}, {%8,%9}, {%0,%1,%2,%3};\n"
        : "+f"(d[0]), "+f"(d[1]), "+f"(d[2]), "+f"(d[3])
        : "r"(a[0]), "r"(a[1]), "r"(a[2]), "r"(a[3]), "r"(b[0]), "r"(b[1]));
}
__device__ __forceinline__ void ldm_x4(unsigned* r, unsigned addr) {
    asm volatile("ldmatrix.sync.aligned.m8n8.x4.shared.b16 {%0,%1,%2,%3}, [%4];"
                 : "=r"(r[0]), "=r"(r[1]), "=r"(r[2]), "=r"(r[3]) : "r"(addr));
}
__device__ __forceinline__ void ldm_x4_t(unsigned* r, unsigned addr) {
    asm volatile("ldmatrix.sync.aligned.m8n8.x4.trans.shared.b16 {%0,%1,%2,%3}, [%4];"
                 : "=r"(r[0]), "=r"(r[1]), "=r"(r[2]), "=r"(r[3]) : "r"(addr));
}
__device__ __forceinline__ void cpa16(unsigned dst, const void* src) {
    asm volatile("cp.async.cg.shared.global [%0], [%1], 16;" :: "r"(dst), "l"(src));
}
__device__ __forceinline__ void cpa_commit() { asm volatile("cp.async.commit_group;"); }
template <int N> __device__ __forceinline__ void cpa_wait() {
    asm volatile("cp.async.wait_group %0;" :: "n"(N));
}
__device__ __forceinline__ unsigned smem_u32(const void* p) {
    return (unsigned)__cvta_generic_to_shared(p);
}

// ---------------------------------------------------------------------------
// prepass: fp32 -> fp16 elementwise
// ---------------------------------------------------------------------------
__global__ void cvt16_kernel(const float* __restrict__ src, __half* __restrict__ dst, int n4) {
    int i = blockIdx.x * blockDim.x + threadIdx.x;
    if (i < n4) {
        float4 v = ((const float4*)src)[i];
        __half2* d2 = (__half2*)dst;
        d2[i * 2]     = __floats2half2_rn(v.x, v.y);
        d2[i * 2 + 1] = __floats2half2_rn(v.z, v.w);
    }
}

// prepass: W[k][n] fp32 -> Wt[n][k] fp16 (32x32 tiles)
__global__ void transpose_cvt_kernel(const float* __restrict__ W, __half* __restrict__ Wt,
                                     int K, int N) {
    __shared__ float t[32][33];
    int k0 = blockIdx.y * 32, n0 = blockIdx.x * 32;
    int tx = threadIdx.x, ty = threadIdx.y;   // 32 x 8
#pragma unroll
    for (int i = 0; i < 4; i++)
        t[ty + i * 8][tx] = W[(size_t)(k0 + ty + i * 8) * N + n0 + tx];
    __syncthreads();
#pragma unroll
    for (int i = 0; i < 4; i++)
        Wt[(size_t)(n0 + ty + i * 8) * K + k0 + tx] = __float2half_rn(t[tx][ty + i * 8]);
}

// ---------------------------------------------------------------------------
// fp16 GEMM: C[M,N] = A[M,K] @ Bt[N,K]^T + bias.
// CTA 128x128, BK=32, 2-stage cp.async. 8 warps 2(m)x4(n), warp 64x32.
// smem row stride 40 halves (80B): ldmatrix rows land on distinct 16B banks.
// QKV mode: fp16 out, cols<EMB scaled by SCALE. else: fp32 out.
// ---------------------------------------------------------------------------
template <bool QKV>
__global__ __launch_bounds__(256) void gemm_f16_kernel(
    const __half* __restrict__ A, const __half* __restrict__ Bt,
    const float* __restrict__ bias, void* __restrict__ Cv, int N, int K)
{
    __shared__ __half As[2][128 * 40];
    __shared__ __half Bs[2][128 * 40];

    const int tid  = threadIdx.x;
    const int lane = tid & 31;
    const int wid  = tid >> 5;
    const int wm   = wid >> 2;
    const int wn   = wid & 3;
    const int r0   = lane >> 2;
    const int c0   = lane & 3;
    const int rowBase = blockIdx.y * 128;
    const int colBase = blockIdx.x * 128;

    // cp.async mapping: 2 chunks (16B = 8 halves) per matrix per thread
    const int ld_row = tid >> 1;              // 0..127
    const int ld_off = (tid & 1) * 2;         // chunk 0/2 (+1)

    const __half* Ap = A  + (size_t)(rowBase + ld_row) * K + ld_off * 8;
    const __half* Bp = Bt + (size_t)(colBase + ld_row) * K + ld_off * 8;

    float acc[4][4][4];
#pragma unroll
    for (int i = 0; i < 4; i++)
#pragma unroll
        for (int j = 0; j < 4; j++)
#pragma unroll
            for (int e = 0; e < 4; e++) acc[i][j][e] = 0.f;

    const int nkt = K / 32;
    const unsigned asB[2] = {smem_u32(As[0]), smem_u32(As[1])};
    const unsigned bsB[2] = {smem_u32(Bs[0]), smem_u32(Bs[1])};
    const unsigned dstOff = (unsigned)(ld_row * 40 + ld_off * 8) * 2;

    // prefetch tile 0
    cpa16(asB[0] + dstOff,      Ap);
    cpa16(asB[0] + dstOff + 16, Ap + 8);
    cpa16(bsB[0] + dstOff,      Bp);
    cpa16(bsB[0] + dstOff + 16, Bp + 8);
    cpa_commit();

    const unsigned fragRow = (unsigned)(lane & 15);
    const unsigned fragK   = (unsigned)((lane >> 4) << 3);

    for (int kt = 0; kt < nkt; kt++) {
        const int s = kt & 1;
        if (kt + 1 < nkt) {
            const int s1 = (kt + 1) & 1;
            const __half* Ap1 = Ap + (kt + 1) * 32;
            const __half* Bp1 = Bp + (kt + 1) * 32;
            cpa16(asB[s1] + dstOff,      Ap1);
            cpa16(asB[s1] + dstOff + 16, Ap1 + 8);
            cpa16(bsB[s1] + dstOff,      Bp1);
            cpa16(bsB[s1] + dstOff + 16, Bp1 + 8);
            cpa_commit();
            cpa_wait<1>();
        } else {
            cpa_wait<0>();
        }
        __syncthreads();

#pragma unroll
        for (int ks = 0; ks < 32; ks += 16) {
            unsigned af[4][4], bf[2][4];
#pragma unroll
            for (int mt = 0; mt < 4; mt++)
                ldm_x4(af[mt], asB[s] + ((wm * 64 + mt * 16 + fragRow) * 40 + ks + fragK) * 2);
#pragma unroll
            for (int np = 0; np < 2; np++)
                ldm_x4(bf[np], bsB[s] + ((wn * 32 + np * 16 + fragRow) * 40 + ks + fragK) * 2);
#pragma unroll
            for (int mt = 0; mt < 4; mt++)
#pragma unroll
                for (int nt = 0; nt < 4; nt++) {
                    unsigned b2[2] = {bf[nt >> 1][nt & 1], bf[nt >> 1][2 + (nt & 1)]};
                    mma_f16(acc[mt][nt], af[mt], b2);
                }
        }
        __syncthreads();
    }

    // epilogue
#pragma unroll
    for (int nt = 0; nt < 4; nt++) {
        int col = colBase + wn * 32 + nt * 8 + (c0 << 1);
        float2 bv = *(const float2*)(bias + col);
        float sc = (QKV && col < EMB) ? SCALE : 1.0f;
#pragma unroll
        for (int mt = 0; mt < 4; mt++) {
            int row = rowBase + wm * 64 + mt * 16 + r0;
            float x0 = (acc[mt][nt][0] + bv.x) * sc;
            float x1 = (acc[mt][nt][1] + bv.y) * sc;
            float x2 = (acc[mt][nt][2] + bv.x) * sc;
            float x3 = (acc[mt][nt][3] + bv.y) * sc;
            if (QKV) {
                __half2* C = (__half2*)Cv;
                C[((size_t)row * N + col) >> 1]       = __floats2half2_rn(x0, x1);
                C[((size_t)(row + 8) * N + col) >> 1] = __floats2half2_rn(x2, x3);
            } else {
                float* C = (float*)Cv;
                *(float2*)(C + (size_t)row * N + col)       = make_float2(x0, x1);
                *(float2*)(C + (size_t)(row + 8) * N + col) = make_float2(x2, x3);
            }
        }
    }
}

// ---------------------------------------------------------------------------
// fp16 tensor-core flash attention.
// Grid (8 qtiles, 12 heads, 8 batch), 256 threads = 8 warps, 16 q-rows/warp.
// Qs [128][72] halves (reused as Ps), Ks/Vs [64][72]. Row stride 144B:
// ldmatrix 8-row phases hit distinct 16B banks. Q pre-scaled by GEMM.
// S: B-frags via ldmatrix on K rows; PV: B-frags via ldmatrix.trans on V rows.
// ---------------------------------------------------------------------------
__global__ __launch_bounds__(256) void attn_f16_kernel(const __half* __restrict__ qkv,
                                                       __half* __restrict__ ctx)
{
    __shared__ __half Qs[128 * 72];   // reused as Ps
    __shared__ __half Ks[64 * 72];
    __shared__ __half Vs[64 * 72];
    __half* Ps = Qs;

    const int tid  = threadIdx.x;
    const int lane = tid & 31;
    const int w    = tid >> 5;
    const int r0   = lane >> 2;
    const int c0   = lane & 3;
    const int qrow = w * 16 + r0;

    const int qt = blockIdx.x;
    const int h  = blockIdx.y;
    const int b  = blockIdx.z;

    const unsigned qsB = smem_u32(Qs);
    const unsigned ksB = smem_u32(Ks);
    const unsigned vsB = smem_u32(Vs);
    const unsigned fragRow = (unsigned)(lane & 15);
    const unsigned fragK   = (unsigned)((lane >> 4) << 3);

    // ---- load Q tile: 128 rows x 64 halves via cp.async (4 chunks/thread) ----
    const __half* qg = qkv + (size_t)(b * SEQ + qt * 128) * E3 + h * HDIM;
    {
        int row = tid >> 1;                  // 0..127
        int off = (tid & 1) * 4;             // chunks off..off+3
#pragma unroll
        for (int i = 0; i < 4; i++)
            cpa16(qsB + (unsigned)(row * 72 + (off + i) * 8) * 2,
                  qg + (size_t)row * E3 + (off + i) * 8);
        cpa_commit();
        cpa_wait<0>();
        __syncthreads();
    }

    // ---- hoist Q fragments: 4 k16 steps ----
    unsigned qf[4][4];
#pragma unroll
    for (int ks = 0; ks < 4; ks++)
        ldm_x4(qf[ks], qsB + ((w * 16 + fragRow) * 72 + ks * 16 + fragK) * 2);

    float accO[8][4];
#pragma unroll
    for (int nt = 0; nt < 8; nt++)
#pragma unroll
        for (int e = 0; e < 4; e++) accO[nt][e] = 0.f;
    float m0 = -1e30f, m1 = -1e30f, l0 = 0.f, l1 = 0.f;

    const __half* kg = qkv + (size_t)b * SEQ * E3 + EMB     + h * HDIM;
    const __half* vg = qkv + (size_t)b * SEQ * E3 + 2 * EMB + h * HDIM;

    const int ld_row = tid >> 2;             // 0..63
    const int ld_off = (tid & 3) * 2;        // chunks off, off+1

    for (int kt = 0; kt < 16; kt++) {
        __syncthreads();   // prior PV reads of Ks/Vs done; Q-frag hoist done (kt=0)
        const __half* kb = kg + (size_t)(kt * 64) * E3 + (size_t)ld_row * E3 + ld_off * 8;
        const __half* vb = vg + (size_t)(kt * 64) * E3 + (size_t)ld_row * E3 + ld_off * 8;
        unsigned dK = ksB + (unsigned)(ld_row * 72 + ld_off * 8) * 2;
        unsigned dV = vsB + (unsigned)(ld_row * 72 + ld_off * 8) * 2;
        cpa16(dK,      kb);
        cpa16(dK + 16, kb + 8);
        cpa16(dV,      vb);
        cpa16(dV + 16, vb + 8);
        cpa_commit();
        cpa_wait<0>();
        __syncthreads();

        // ---- S = Q K^T : 16 rows x 64 keys per warp ----
        float accS[8][4];
#pragma unroll
        for (int nt = 0; nt < 8; nt++)
#pragma unroll
            for (int e = 0; e < 4; e++) accS[nt][e] = 0.f;

#pragma unroll
        for (int ks = 0; ks < 4; ks++) {
#pragma unroll
            for (int np = 0; np < 4; np++) {
                unsigned bf[4];
                ldm_x4(bf, ksB + ((np * 16 + fragRow) * 72 + ks * 16 + fragK) * 2);
                unsigned b0[2] = {bf[0], bf[2]};
                unsigned b1[2] = {bf[1], bf[3]};
                mma_f16(accS[np * 2],     qf[ks], b0);
                mma_f16(accS[np * 2 + 1], qf[ks], b1);
            }
        }

        // ---- online softmax (rows qrow, qrow+8) ----
        float mx0 = -1e30f, mx1 = -1e30f;
#pragma unroll
        for (int nt = 0; nt < 8; nt++) {
            mx0 = fmaxf(mx0, fmaxf(accS[nt][0], accS[nt][1]));
            mx1 = fmaxf(mx1, fmaxf(accS[nt][2], accS[nt][3]));
        }
#pragma unroll
        for (int off = 1; off < 4; off <<= 1) {
            mx0 = fmaxf(mx0, __shfl_xor_sync(0xffffffffu, mx0, off));
            mx1 = fmaxf(mx1, __shfl_xor_sync(0xffffffffu, mx1, off));
        }
        float mn0 = fmaxf(m0, mx0), mn1 = fmaxf(m1, mx1);
        float alpha0 = __expf(m0 - mn0), alpha1 = __expf(m1 - mn1);
        m0 = mn0; m1 = mn1;

        __syncwarp();   // lagging lanes finish prior PV ldmatrix of Ps

        float s0 = 0.f, s1 = 0.f;
        __half2* P2 = (__half2*)Ps;
#pragma unroll
        for (int nt = 0; nt < 8; nt++) {
            float p0 = __expf(accS[nt][0] - mn0);
            float p1 = __expf(accS[nt][1] - mn0);
            float p2 = __expf(accS[nt][2] - mn1);
            float p3 = __expf(accS[nt][3] - mn1);
            s0 += p0 + p1;
            s1 += p2 + p3;
            int cl = nt * 8 + (c0 << 1);
            P2[(qrow * 72 + cl) >> 1]       = __floats2half2_rn(p0, p1);
            P2[((qrow + 8) * 72 + cl) >> 1] = __floats2half2_rn(p2, p3);
        }
#pragma unroll
        for (int off = 1; off < 4; off <<= 1) {
            s0 += __shfl_xor_sync(0xffffffffu, s0, off);
            s1 += __shfl_xor_sync(0xffffffffu, s1, off);
        }
        l0 = l0 * alpha0 + s0;
        l1 = l1 * alpha1 + s1;
#pragma unroll
        for (int nt = 0; nt < 8; nt++) {
            accO[nt][0] *= alpha0; accO[nt][1] *= alpha0;
            accO[nt][2] *= alpha1; accO[nt][3] *= alpha1;
        }
        __syncwarp();   // P rows warp-private

        // ---- O += P V ----
#pragma unroll
        for (int ks = 0; ks < 4; ks++) {    // key 16-chunks
            unsigned pf[4];
            ldm_x4(pf, qsB + ((w * 16 + fragRow) * 72 + ks * 16 + fragK) * 2);
#pragma unroll
            for (int np = 0; np < 4; np++) { // d 16-chunks
                unsigned bf[4];
                ldm_x4_t(bf, vsB + ((ks * 16 + fragRow) * 72 + np * 16 + fragK) * 2);
                unsigned b0[2] = {bf[0], bf[1]};
                unsigned b1[2] = {bf[2], bf[3]};
                mma_f16(accO[np * 2],     pf, b0);
                mma_f16(accO[np * 2 + 1], pf, b1);
            }
        }
    }

    // ---- normalize + write ctx16 ----
    float inv0 = 1.f / l0, inv1 = 1.f / l1;
    __half2* ob = (__half2*)(ctx + (size_t)(b * SEQ + qt * 128) * EMB + h * HDIM);
#pragma unroll
    for (int nt = 0; nt < 8; nt++) {
        int col = nt * 8 + (c0 << 1);
        ob[((size_t)qrow * EMB + col) >> 1] =
            __floats2half2_rn(accO[nt][0] * inv0, accO[nt][1] * inv0);
        ob[((size_t)(qrow + 8) * EMB + col) >> 1] =
            __floats2half2_rn(accO[nt][2] * inv1, accO[nt][3] * inv1);
    }
}

// ---------------------------------------------------------------------------
extern "C" void kernel_launch(void* const* d_in, const int* in_sizes, int n_in,
                              void* d_out, int out_size)
{
    const float* hs     = (const float*)d_in[0];
    const float* qkv_w  = (const float*)d_in[1];
    const float* qkv_b  = (const float*)d_in[2];
    const float* proj_w = (const float*)d_in[3];
    const float* proj_b = (const float*)d_in[4];
    float* out = (float*)d_out;

    __half *hs16, *qkvwt, *projwt, *qkv16, *ctx16;
    cudaGetSymbolAddress((void**)&hs16,   g_hs16);
    cudaGetSymbolAddress((void**)&qkvwt,  g_qkvwt);
    cudaGetSymbolAddress((void**)&projwt, g_projwt);
    cudaGetSymbolAddress((void**)&qkv16,  g_qkv16);
    cudaGetSymbolAddress((void**)&ctx16,  g_ctx16);

    // prepass: convert / transpose to fp16
    {
        int n4 = MROWS * EMB / 4;
        cvt16_kernel<<<(n4 + 255) / 256, 256>>>(hs, hs16, n4);
        transpose_cvt_kernel<<<dim3(E3 / 32, EMB / 32), dim3(32, 8)>>>(qkv_w, qkvwt, EMB, E3);
        transpose_cvt_kernel<<<dim3(EMB / 32, EMB / 32), dim3(32, 8)>>>(proj_w, projwt, EMB, EMB);
    }

    // 1) QKV projection (fp16 out, Q pre-scaled)
    gemm_f16_kernel<true><<<dim3(E3 / 128, MROWS / 128), 256>>>(
        hs16, qkvwt, qkv_b, qkv16, E3, EMB);

    // 2) fp16 tensor-core flash attention
    attn_f16_kernel<<<dim3(SEQ / 128, NHEADS, BATCH), 256>>>(qkv16, ctx16);

    // 3) output projection (fp32 out)
    gemm_f16_kernel<false><<<dim3(EMB / 128, MROWS / 128), 256>>>(
        ctx16, projwt, proj_b, out, EMB, EMB);
}

// round 10
// speedup vs baseline: 6.3880x; 1.0424x over previous
#include <cuda_runtime.h>
#include <cuda_fp16.h>

#define BATCH  8
#define SEQ    1024
#define EMB    768
#define NHEADS 12
#define HDIM   64
#define E3     2304
#define MROWS  8192
#define SCALE  0.125f

// Scratch (no cudaMalloc allowed)
__device__ __half g_hs16[(size_t)MROWS * EMB];     // hidden fp16
__device__ __half g_qkvwt[(size_t)E3 * EMB];       // qkv_w^T  [n][k] fp16
__device__ __half g_projwt[(size_t)EMB * EMB];     // proj_w^T [n][k] fp16
__device__ __half g_qkv16[(size_t)MROWS * E3];     // QKV output fp16 (Q pre-scaled)
__device__ __half g_ctx16[(size_t)MROWS * EMB];    // attention output fp16

// ---------------------------------------------------------------------------
// helpers
// ---------------------------------------------------------------------------
__device__ __forceinline__ void mma_f16(float* d, const unsigned* a, const unsigned* b) {
    asm volatile(
        "mma.sync.aligned.m16n8k16.row.col.f32.f16.f16.f32 "
        "{%0,%1,%2,%3}, {%4,%5,%6,%7}, {%8,%9}, {%0,%1,%2,%3};\n"
        : "+f"(d[0]), "+f"(d[1]), "+f"(d[2]), "+f"(d[3])
        : "r"(a[0]), "r"(a[1]), "r"(a[2]), "r"(a[3]), "r"(b[0]), "r"(b[1]));
}
__device__ __forceinline__ void ldm_x4(unsigned* r, unsigned addr) {
    asm volatile("ldmatrix.sync.aligned.m8n8.x4.shared.b16 {%0,%1,%2,%3}, [%4];"
                 : "=r"(r[0]), "=r"(r[1]), "=r"(r[2]), "=r"(r[3]) : "r"(addr));
}
__device__ __forceinline__ void ldm_x4_t(unsigned* r, unsigned addr) {
    asm volatile("ldmatrix.sync.aligned.m8n8.x4.trans.shared.b16 {%0,%1,%2,%3}, [%4];"
                 : "=r"(r[0]), "=r"(r[1]), "=r"(r[2]), "=r"(r[3]) : "r"(addr));
}
__device__ __forceinline__ void cpa16(unsigned dst, const void* src) {
    asm volatile("cp.async.cg.shared.global [%0], [%1], 16;" :: "r"(dst), "l"(src));
}
__device__ __forceinline__ void cpa_commit() { asm volatile("cp.async.commit_group;"); }
template <int N> __device__ __forceinline__ void cpa_wait() {
    asm volatile("cp.async.wait_group %0;" :: "n"(N));
}
__device__ __forceinline__ unsigned smem_u32(const void* p) {
    return (unsigned)__cvta_generic_to_shared(p);
}

// ---------------------------------------------------------------------------
// prepass: fp32 -> fp16 elementwise
// ---------------------------------------------------------------------------
__global__ void cvt16_kernel(const float* __restrict__ src, __half* __restrict__ dst, int n4) {
    int i = blockIdx.x * blockDim.x + threadIdx.x;
    if (i < n4) {
        float4 v = ((const float4*)src)[i];
        __half2* d2 = (__half2*)dst;
        d2[i * 2]     = __floats2half2_rn(v.x, v.y);
        d2[i * 2 + 1] = __floats2half2_rn(v.z, v.w);
    }
}

// prepass: W[k][n] fp32 -> Wt[n][k] fp16 (32x32 tiles)
__global__ void transpose_cvt_kernel(const float* __restrict__ W, __half* __restrict__ Wt,
                                     int K, int N) {
    __shared__ float t[32][33];
    int k0 = blockIdx.y * 32, n0 = blockIdx.x * 32;
    int tx = threadIdx.x, ty = threadIdx.y;   // 32 x 8
#pragma unroll
    for (int i = 0; i < 4; i++)
        t[ty + i * 8][tx] = W[(size_t)(k0 + ty + i * 8) * N + n0 + tx];
    __syncthreads();
#pragma unroll
    for (int i = 0; i < 4; i++)
        Wt[(size_t)(n0 + ty + i * 8) * K + k0 + tx] = __float2half_rn(t[tx][ty + i * 8]);
}

// ---------------------------------------------------------------------------
// fp16 GEMM: C[M,N] = A[M,K] @ Bt[N,K]^T + bias.
// CTA 128x128, BK=32, 3-stage cp.async ring, ONE __syncthreads per K-iter.
// Schedule per iter: wait(tile kt) -> sync -> prefetch kt+2 -> compute kt.
// Prefetch writes stage (kt+2)%3 == (kt-1)%3; the sync proved all threads
// finished compute kt-1, so the overwrite is safe and overlaps compute kt.
// ---------------------------------------------------------------------------
template <bool QKV>
__global__ __launch_bounds__(256) void gemm_f16_kernel(
    const __half* __restrict__ A, const __half* __restrict__ Bt,
    const float* __restrict__ bias, void* __restrict__ Cv, int N, int K)
{
    extern __shared__ __half dsm[];
    // layout: A stages [3][128*40], then B stages [3][128*40]
    const unsigned aB = smem_u32(dsm);
    const unsigned bB = aB + 3 * 128 * 40 * 2;

    const int tid  = threadIdx.x;
    const int lane = tid & 31;
    const int wid  = tid >> 5;
    const int wm   = wid >> 2;
    const int wn   = wid & 3;
    const int r0   = lane >> 2;
    const int c0   = lane & 3;
    const int rowBase = blockIdx.y * 128;
    const int colBase = blockIdx.x * 128;

    const int ld_row = tid >> 1;              // 0..127
    const int ld_off = (tid & 1) * 2;         // 16B chunk 0/2 (+1)

    const __half* Ap = A  + (size_t)(rowBase + ld_row) * K + ld_off * 8;
    const __half* Bp = Bt + (size_t)(colBase + ld_row) * K + ld_off * 8;

    const unsigned dstOff = (unsigned)(ld_row * 40 + ld_off * 8) * 2;
    const unsigned stageB = 128 * 40 * 2;     // bytes per stage

    float acc[4][4][4];
#pragma unroll
    for (int i = 0; i < 4; i++)
#pragma unroll
        for (int j = 0; j < 4; j++)
#pragma unroll
            for (int e = 0; e < 4; e++) acc[i][j][e] = 0.f;

    const int nkt = K / 32;

    // preload tiles 0,1
#pragma unroll
    for (int t = 0; t < 2; t++) {
        const __half* Apt = Ap + t * 32;
        const __half* Bpt = Bp + t * 32;
        cpa16(aB + t * stageB + dstOff,      Apt);
        cpa16(aB + t * stageB + dstOff + 16, Apt + 8);
        cpa16(bB + t * stageB + dstOff,      Bpt);
        cpa16(bB + t * stageB + dstOff + 16, Bpt + 8);
        cpa_commit();
    }

    const unsigned fragRow = (unsigned)(lane & 15);
    const unsigned fragK   = (unsigned)((lane >> 4) << 3);

    for (int kt = 0; kt < nkt; kt++) {
        if (kt + 1 < nkt) cpa_wait<1>(); else cpa_wait<0>();
        __syncthreads();

        if (kt + 2 < nkt) {
            const int s2 = (kt + 2) % 3;
            const __half* Ap2 = Ap + (kt + 2) * 32;
            const __half* Bp2 = Bp + (kt + 2) * 32;
            cpa16(aB + s2 * stageB + dstOff,      Ap2);
            cpa16(aB + s2 * stageB + dstOff + 16, Ap2 + 8);
            cpa16(bB + s2 * stageB + dstOff,      Bp2);
            cpa16(bB + s2 * stageB + dstOff + 16, Bp2 + 8);
            cpa_commit();
        }

        const unsigned as = aB + (kt % 3) * stageB;
        const unsigned bs = bB + (kt % 3) * stageB;
#pragma unroll
        for (int ks = 0; ks < 32; ks += 16) {
            unsigned af[4][4], bf[2][4];
#pragma unroll
            for (int mt = 0; mt < 4; mt++)
                ldm_x4(af[mt], as + ((wm * 64 + mt * 16 + fragRow) * 40 + ks + fragK) * 2);
#pragma unroll
            for (int np = 0; np < 2; np++)
                ldm_x4(bf[np], bs + ((wn * 32 + np * 16 + fragRow) * 40 + ks + fragK) * 2);
#pragma unroll
            for (int mt = 0; mt < 4; mt++)
#pragma unroll
                for (int nt = 0; nt < 4; nt++) {
                    unsigned b2[2] = {bf[nt >> 1][nt & 1], bf[nt >> 1][2 + (nt & 1)]};
                    mma_f16(acc[mt][nt], af[mt], b2);
                }
        }
    }

    // epilogue
#pragma unroll
    for (int nt = 0; nt < 4; nt++) {
        int col = colBase + wn * 32 + nt * 8 + (c0 << 1);
        float2 bv = *(const float2*)(bias + col);
        float sc = (QKV && col < EMB) ? SCALE : 1.0f;
#pragma unroll
        for (int mt = 0; mt < 4; mt++) {
            int row = rowBase + wm * 64 + mt * 16 + r0;
            float x0 = (acc[mt][nt][0] + bv.x) * sc;
            float x1 = (acc[mt][nt][1] + bv.y) * sc;
            float x2 = (acc[mt][nt][2] + bv.x) * sc;
            float x3 = (acc[mt][nt][3] + bv.y) * sc;
            if (QKV) {
                __half2* C = (__half2*)Cv;
                C[((size_t)row * N + col) >> 1]       = __floats2half2_rn(x0, x1);
                C[((size_t)(row + 8) * N + col) >> 1] = __floats2half2_rn(x2, x3);
            } else {
                float* C = (float*)Cv;
                *(float2*)(C + (size_t)row * N + col)       = make_float2(x0, x1);
                *(float2*)(C + (size_t)(row + 8) * N + col) = make_float2(x2, x3);
            }
        }
    }
}

// ---------------------------------------------------------------------------
// fp16 tensor-core flash attention, 3-stage K/V cp.async ring.
// Grid (8 qtiles, 12 heads, 8 batch), 256 threads = 8 warps, 16 q-rows/warp.
// Same single-sync schedule as the GEMM: wait(kt) -> sync -> prefetch kt+2
// -> compute kt. Q region reused as P (warp-private rows).
// ---------------------------------------------------------------------------
__global__ __launch_bounds__(256) void attn_f16_kernel(const __half* __restrict__ qkv,
                                                       __half* __restrict__ ctx)
{
    extern __shared__ __half asm_[];
    const unsigned qsB = smem_u32(asm_);               // [128][72]
    const unsigned kB  = qsB + 128 * 72 * 2;           // 3 x [64][72]
    const unsigned vB  = kB + 3 * 64 * 72 * 2;         // 3 x [64][72]
    const unsigned kvStage = 64 * 72 * 2;

    const int tid  = threadIdx.x;
    const int lane = tid & 31;
    const int w    = tid >> 5;
    const int r0   = lane >> 2;
    const int c0   = lane & 3;
    const int qrow = w * 16 + r0;

    const int qt = blockIdx.x;
    const int h  = blockIdx.y;
    const int b  = blockIdx.z;

    const unsigned fragRow = (unsigned)(lane & 15);
    const unsigned fragK   = (unsigned)((lane >> 4) << 3);

    // ---- load Q tile: 128 rows x 64 halves via cp.async ----
    const __half* qg = qkv + (size_t)(b * SEQ + qt * 128) * E3 + h * HDIM;
    {
        int row = tid >> 1;
        int off = (tid & 1) * 4;
#pragma unroll
        for (int i = 0; i < 4; i++)
            cpa16(qsB + (unsigned)(row * 72 + (off + i) * 8) * 2,
                  qg + (size_t)row * E3 + (off + i) * 8);
        cpa_commit();
        cpa_wait<0>();
        __syncthreads();
    }

    // ---- hoist Q fragments ----
    unsigned qf[4][4];
#pragma unroll
    for (int ks = 0; ks < 4; ks++)
        ldm_x4(qf[ks], qsB + ((w * 16 + fragRow) * 72 + ks * 16 + fragK) * 2);

    float accO[8][4];
#pragma unroll
    for (int nt = 0; nt < 8; nt++)
#pragma unroll
        for (int e = 0; e < 4; e++) accO[nt][e] = 0.f;
    float m0 = -1e30f, m1 = -1e30f, l0 = 0.f, l1 = 0.f;

    const __half* kg = qkv + (size_t)b * SEQ * E3 + EMB     + h * HDIM;
    const __half* vg = qkv + (size_t)b * SEQ * E3 + 2 * EMB + h * HDIM;

    const int ld_row = tid >> 2;             // 0..63
    const int ld_off = (tid & 3) * 2;        // 16B chunks

    const size_t ldbase = (size_t)ld_row * E3 + ld_off * 8;
    const unsigned dOff = (unsigned)(ld_row * 72 + ld_off * 8) * 2;

    // preload kv tiles 0,1
#pragma unroll
    for (int t = 0; t < 2; t++) {
        const __half* kb = kg + (size_t)(t * 64) * E3 + ldbase;
        const __half* vb = vg + (size_t)(t * 64) * E3 + ldbase;
        cpa16(kB + t * kvStage + dOff,      kb);
        cpa16(kB + t * kvStage + dOff + 16, kb + 8);
        cpa16(vB + t * kvStage + dOff,      vb);
        cpa16(vB + t * kvStage + dOff + 16, vb + 8);
        cpa_commit();
    }

    for (int kt = 0; kt < 16; kt++) {
        if (kt + 1 < 16) cpa_wait<1>(); else cpa_wait<0>();
        __syncthreads();

        if (kt + 2 < 16) {
            const int s2 = (kt + 2) % 3;
            const __half* kb = kg + (size_t)((kt + 2) * 64) * E3 + ldbase;
            const __half* vb = vg + (size_t)((kt + 2) * 64) * E3 + ldbase;
            cpa16(kB + s2 * kvStage + dOff,      kb);
            cpa16(kB + s2 * kvStage + dOff + 16, kb + 8);
            cpa16(vB + s2 * kvStage + dOff,      vb);
            cpa16(vB + s2 * kvStage + dOff + 16, vb + 8);
            cpa_commit();
        }

        const unsigned ksS = kB + (kt % 3) * kvStage;
        const unsigned vsS = vB + (kt % 3) * kvStage;

        // ---- S = Q K^T : 16 rows x 64 keys per warp ----
        float accS[8][4];
#pragma unroll
        for (int nt = 0; nt < 8; nt++)
#pragma unroll
            for (int e = 0; e < 4; e++) accS[nt][e] = 0.f;

#pragma unroll
        for (int ks = 0; ks < 4; ks++) {
#pragma unroll
            for (int np = 0; np < 4; np++) {
                unsigned bf[4];
                ldm_x4(bf, ksS + ((np * 16 + fragRow) * 72 + ks * 16 + fragK) * 2);
                unsigned b0[2] = {bf[0], bf[2]};
                unsigned b1[2] = {bf[1], bf[3]};
                mma_f16(accS[np * 2],     qf[ks], b0);
                mma_f16(accS[np * 2 + 1], qf[ks], b1);
            }
        }

        // ---- online softmax (rows qrow, qrow+8) ----
        float mx0 = -1e30f, mx1 = -1e30f;
#pragma unroll
        for (int nt = 0; nt < 8; nt++) {
            mx0 = fmaxf(mx0, fmaxf(accS[nt][0], accS[nt][1]));
            mx1 = fmaxf(mx1, fmaxf(accS[nt][2], accS[nt][3]));
        }
#pragma unroll
        for (int off = 1; off < 4; off <<= 1) {
            mx0 = fmaxf(mx0, __shfl_xor_sync(0xffffffffu, mx0, off));
            mx1 = fmaxf(mx1, __shfl_xor_sync(0xffffffffu, mx1, off));
        }
        float mn0 = fmaxf(m0, mx0), mn1 = fmaxf(m1, mx1);
        float alpha0 = __expf(m0 - mn0), alpha1 = __expf(m1 - mn1);
        m0 = mn0; m1 = mn1;

        __syncwarp();   // lagging lanes finish prior PV ldmatrix of Ps

        float s0 = 0.f, s1 = 0.f;
        __half2* P2 = (__half2*)asm_;
#pragma unroll
        for (int nt = 0; nt < 8; nt++) {
            float p0 = __expf(accS[nt][0] - mn0);
            float p1 = __expf(accS[nt][1] - mn0);
            float p2 = __expf(accS[nt][2] - mn1);
            float p3 = __expf(accS[nt][3] - mn1);
            s0 += p0 + p1;
            s1 += p2 + p3;
            int cl = nt * 8 + (c0 << 1);
            P2[(qrow * 72 + cl) >> 1]       = __floats2half2_rn(p0, p1);
            P2[((qrow + 8) * 72 + cl) >> 1] = __floats2half2_rn(p2, p3);
        }
#pragma unroll
        for (int off = 1; off < 4; off <<= 1) {
            s0 += __shfl_xor_sync(0xffffffffu, s0, off);
            s1 += __shfl_xor_sync(0xffffffffu, s1, off);
        }
        l0 = l0 * alpha0 + s0;
        l1 = l1 * alpha1 + s1;
#pragma unroll
        for (int nt = 0; nt < 8; nt++) {
            accO[nt][0] *= alpha0; accO[nt][1] *= alpha0;
            accO[nt][2] *= alpha1; accO[nt][3] *= alpha1;
        }
        __syncwarp();   // P rows warp-private

        // ---- O += P V ----
#pragma unroll
        for (int ks = 0; ks < 4; ks++) {
            unsigned pf[4];
            ldm_x4(pf, qsB + ((w * 16 + fragRow) * 72 + ks * 16 + fragK) * 2);
#pragma unroll
            for (int np = 0; np < 4; np++) {
                unsigned bf[4];
                ldm_x4_t(bf, vsS + ((ks * 16 + fragRow) * 72 + np * 16 + fragK) * 2);
                unsigned b0[2] = {bf[0], bf[1]};
                unsigned b1[2] = {bf[2], bf[3]};
                mma_f16(accO[np * 2],     pf, b0);
                mma_f16(accO[np * 2 + 1], pf, b1);
            }
        }
    }

    // ---- normalize + write ctx16 ----
    float inv0 = 1.f / l0, inv1 = 1.f / l1;
    __half2* ob = (__half2*)(ctx + (size_t)(b * SEQ + qt * 128) * EMB + h * HDIM);
#pragma unroll
    for (int nt = 0; nt < 8; nt++) {
        int col = nt * 8 + (c0 << 1);
        ob[((size_t)qrow * EMB + col) >> 1] =
            __floats2half2_rn(accO[nt][0] * inv0, accO[nt][1] * inv0);
        ob[((size_t)(qrow + 8) * EMB + col) >> 1] =
            __floats2half2_rn(accO[nt][2] * inv1, accO[nt][3] * inv1);
    }
}

// ---------------------------------------------------------------------------
extern "C" void kernel_launch(void* const* d_in, const int* in_sizes, int n_in,
                              void* d_out, int out_size)
{
    const float* hs     = (const float*)d_in[0];
    const float* qkv_w  = (const float*)d_in[1];
    const float* qkv_b  = (const float*)d_in[2];
    const float* proj_w = (const float*)d_in[3];
    const float* proj_b = (const float*)d_in[4];
    float* out = (float*)d_out;

    __half *hs16, *qkvwt, *projwt, *qkv16, *ctx16;
    cudaGetSymbolAddress((void**)&hs16,   g_hs16);
    cudaGetSymbolAddress((void**)&qkvwt,  g_qkvwt);
    cudaGetSymbolAddress((void**)&projwt, g_projwt);
    cudaGetSymbolAddress((void**)&qkv16,  g_qkv16);
    cudaGetSymbolAddress((void**)&ctx16,  g_ctx16);

    const int gemm_smem = 6 * 128 * 40 * 2;                       // 61440 B
    const int attn_smem = (128 * 72 + 6 * 64 * 72) * 2;           // 73728 B
    cudaFuncSetAttribute(gemm_f16_kernel<true>,
                         cudaFuncAttributeMaxDynamicSharedMemorySize, gemm_smem);
    cudaFuncSetAttribute(gemm_f16_kernel<false>,
                         cudaFuncAttributeMaxDynamicSharedMemorySize, gemm_smem);
    cudaFuncSetAttribute(attn_f16_kernel,
                         cudaFuncAttributeMaxDynamicSharedMemorySize, attn_smem);

    // prepass: convert / transpose to fp16
    {
        int n4 = MROWS * EMB / 4;
        cvt16_kernel<<<(n4 + 255) / 256, 256>>>(hs, hs16, n4);
        transpose_cvt_kernel<<<dim3(E3 / 32, EMB / 32), dim3(32, 8)>>>(qkv_w, qkvwt, EMB, E3);
        transpose_cvt_kernel<<<dim3(EMB / 32, EMB / 32), dim3(32, 8)>>>(proj_w, projwt, EMB, EMB);
    }

    // 1) QKV projection (fp16 out, Q pre-scaled)
    gemm_f16_kernel<true><<<dim3(E3 / 128, MROWS / 128), 256, gemm_smem>>>(
        hs16, qkvwt, qkv_b, qkv16, E3, EMB);

    // 2) fp16 tensor-core flash attention
    attn_f16_kernel<<<dim3(SEQ / 128, NHEADS, BATCH), 256, attn_smem>>>(qkv16, ctx16);

    // 3) output projection (fp32 out)
    gemm_f16_kernel<false><<<dim3(EMB / 128, MROWS / 128), 256, gemm_smem>>>(
        ctx16, projwt, proj_b, out, EMB, EMB);
}